// round 11
// baseline (speedup 1.0000x reference)
#include <cuda_runtime.h>

// GridPooling: counting-sort by cell + warp-per-cell float4 gather-max.
// R10 vs R9 (70.1us): pool blocks own 8 cells whose pidx ranges are
// contiguous (scan pos-order); indices staged cooperatively in smem ->
// no shuffles, no duplicate tail loads, one metadata prologue per 8 cells.
// Scatter reads metadata 4-wide (uint4). Pool back to 4-wide bodies (32 regs).

#define GRID_DIM   32
#define NUM_CELLS  (GRID_DIM * GRID_DIM * GRID_DIM)   // 32768
#define FEAT       128
#define MAX_POINTS (1 << 20)
#define CPB        8        // cells per pool block
#define IDX_CAP    4096     // smem index staging capacity (ints)

__device__ int          g_count  [NUM_CELLS];       // zero at load; pool re-zeroes
__device__ int          g_offset [NUM_CELLS];       // cell-indexed (scatter)
__device__ int          g_off_pos[NUM_CELLS + 1];   // pos-ordered + sentinel (pool)
__device__ unsigned int g_cellrank[MAX_POINTS];     // cell | (rank << 16)
__device__ int          g_pidx   [MAX_POINTS];

// scan ownership: thread t, slot j -> cell = t + j*1024, pos = t*32 + j.
// inverse: cell(pos) = (pos >> 5) + (pos & 31) * 1024.

__device__ __forceinline__ int cell_of(float x, float y, float z)
{
    int ix = __float2int_rd(x * (float)GRID_DIM);
    int iy = __float2int_rd(y * (float)GRID_DIM);
    int iz = __float2int_rd(z * (float)GRID_DIM);
    ix = min(max(ix, 0), GRID_DIM - 1);
    iy = min(max(iy, 0), GRID_DIM - 1);
    iz = min(max(iz, 0), GRID_DIM - 1);
    return ix * (GRID_DIM * GRID_DIM) + iy * GRID_DIM + iz;
}

// Phase 1: cell id + histogram; atomicAdd return value = within-cell rank.
__global__ __launch_bounds__(256)
void cell_kernel(const float* __restrict__ pts, int n)
{
    const int q  = blockIdx.x * blockDim.x + threadIdx.x;
    const int p0 = q * 4;
    if (p0 >= n) return;

    if (p0 + 4 <= n) {
        const float4* p4 = reinterpret_cast<const float4*>(pts);
        float4 a = p4[q * 3 + 0];
        float4 b = p4[q * 3 + 1];
        float4 c = p4[q * 3 + 2];
        float xs[4] = {a.x, a.w, b.z, c.y};
        float ys[4] = {a.y, b.x, b.w, c.z};
        float zs[4] = {a.z, b.y, c.x, c.w};
        #pragma unroll
        for (int k = 0; k < 4; k++) {
            int c_ = cell_of(xs[k], ys[k], zs[k]);
            unsigned int r = (unsigned int)atomicAdd(&g_count[c_], 1);
            g_cellrank[p0 + k] = (unsigned int)c_ | (r << 16);
        }
    } else {
        for (int p = p0; p < n; p++) {
            int c_ = cell_of(pts[3 * p], pts[3 * p + 1], pts[3 * p + 2]);
            unsigned int r = (unsigned int)atomicAdd(&g_count[c_], 1);
            g_cellrank[p] = (unsigned int)c_ | (r << 16);
        }
    }
}

// Phase 2: exclusive scan, one 1024-thread block, coalesced ownership.
// Emits g_offset (cell-indexed) and g_off_pos (pos-ordered, contiguous).
__global__ __launch_bounds__(1024)
void scan_kernel()
{
    __shared__ int warp_sums[32];
    const int t    = threadIdx.x;
    const int lane = t & 31;
    const int w    = t >> 5;

    int vals[32];
    #pragma unroll
    for (int j = 0; j < 32; j++)
        vals[j] = g_count[t + j * 1024];     // MLP=32, coalesced

    int local[32];
    int s = 0;
    #pragma unroll
    for (int j = 0; j < 32; j++) { local[j] = s; s += vals[j]; }

    int v = s;
    #pragma unroll
    for (int d = 1; d < 32; d <<= 1) {
        int nbr = __shfl_up_sync(0xffffffffu, v, d);
        if (lane >= d) v += nbr;
    }
    if (lane == 31) warp_sums[w] = v;
    __syncthreads();
    if (w == 0) {
        int x = warp_sums[lane];
        #pragma unroll
        for (int d = 1; d < 32; d <<= 1) {
            int nbr = __shfl_up_sync(0xffffffffu, x, d);
            if (lane >= d) x += nbr;
        }
        warp_sums[lane] = x;
    }
    __syncthreads();

    const int excl = v - s + (w > 0 ? warp_sums[w - 1] : 0);
    #pragma unroll
    for (int j = 0; j < 32; j++) {
        const int o = excl + local[j];
        g_offset [t + j * 1024] = o;   // coalesced
        g_off_pos[t * 32 + j]   = o;   // contiguous per thread
    }
    if (t == 0) g_off_pos[NUM_CELLS] = warp_sums[31];  // sentinel = n
}

// Phase 3: atomic-free scatter, 4 points per thread (uint4 metadata load,
// 4 independent offset loads in flight).
__global__ __launch_bounds__(256)
void scatter_kernel(int n)
{
    const int q  = blockIdx.x * blockDim.x + threadIdx.x;
    const int p0 = q * 4;
    if (p0 >= n) return;

    if (p0 + 4 <= n) {
        uint4 cr = reinterpret_cast<const uint4*>(g_cellrank)[q];
        int o0 = g_offset[cr.x & 0xffffu];
        int o1 = g_offset[cr.y & 0xffffu];
        int o2 = g_offset[cr.z & 0xffffu];
        int o3 = g_offset[cr.w & 0xffffu];
        g_pidx[o0 + (int)(cr.x >> 16)] = p0 + 0;
        g_pidx[o1 + (int)(cr.y >> 16)] = p0 + 1;
        g_pidx[o2 + (int)(cr.z >> 16)] = p0 + 2;
        g_pidx[o3 + (int)(cr.w >> 16)] = p0 + 3;
    } else {
        for (int p = p0; p < n; p++) {
            unsigned int cr = g_cellrank[p];
            g_pidx[g_offset[cr & 0xffffu] + (int)(cr >> 16)] = p;
        }
    }
}

// Phase 4: 256-thread block = 8 cells (one warp each). The 8 cells' pidx
// ranges are contiguous in pos-order: staged into smem with one coalesced
// cooperative pass. Warps read indices as broadcast LDS -- no shuffles.
__device__ __forceinline__ float4 max4(float4 a, float4 b)
{
    return make_float4(fmaxf(a.x, b.x), fmaxf(a.y, b.y),
                       fmaxf(a.z, b.z), fmaxf(a.w, b.w));
}

__device__ __forceinline__ float4 pool_range(const int* __restrict__ ip,
                                             int i0, int i1, int lane,
                                             const float4* __restrict__ feats4)
{
    float4 m = make_float4(0.f, 0.f, 0.f, 0.f);  // max(.,0) + empty cells
    int i = i0;
    for (; i + 4 <= i1; i += 4) {
        int j0 = ip[i], j1 = ip[i + 1], j2 = ip[i + 2], j3 = ip[i + 3];
        float4 a = feats4[(size_t)j0 * (FEAT / 4) + lane];
        float4 b = feats4[(size_t)j1 * (FEAT / 4) + lane];
        float4 c = feats4[(size_t)j2 * (FEAT / 4) + lane];
        float4 d = feats4[(size_t)j3 * (FEAT / 4) + lane];
        m = max4(m, max4(max4(a, b), max4(c, d)));
    }
    for (; i < i1; i++)
        m = max4(m, feats4[(size_t)ip[i] * (FEAT / 4) + lane]);
    return m;
}

__global__ __launch_bounds__(256)
void pool_kernel(const float4* __restrict__ feats4, float4* __restrict__ out4)
{
    __shared__ int s_idx[IDX_CAP];
    __shared__ int s_off[CPB + 1];

    const int t    = threadIdx.x;
    const int warp = t >> 5;
    const int lane = t & 31;
    const int pos0 = blockIdx.x * CPB;

    if (t <= CPB) s_off[t] = g_off_pos[pos0 + t];
    __syncthreads();

    const int base = s_off[0];
    const int tot  = s_off[CPB] - base;
    const bool use_smem = (tot <= IDX_CAP);
    if (use_smem)
        for (int i = t; i < tot; i += 256) s_idx[i] = g_pidx[base + i];
    __syncthreads();

    const int pos  = pos0 + warp;
    const int cell = (pos >> 5) + (pos & 31) * 1024;   // inverse of scan order
    const int i0   = s_off[warp]     - base;
    const int i1   = s_off[warp + 1] - base;

    float4 m = use_smem
             ? pool_range(s_idx,          i0, i1, lane, feats4)
             : pool_range(g_pidx + base,  i0, i1, lane, feats4);

    out4[(size_t)cell * (FEAT / 4) + lane] = m;

    if (lane == 0) g_count[cell] = 0;   // restore invariant for next replay
}

extern "C" void kernel_launch(void* const* d_in, const int* in_sizes, int n_in,
                              void* d_out, int out_size)
{
    const float* feats = (const float*)d_in[0];   // [N, 128]
    const float* pts   = (const float*)d_in[1];   // [N, 3]

    const int n = in_sizes[1] / 3;

    const int groups = (n + 3) / 4;
    cell_kernel   <<<(groups + 255) / 256, 256>>>(pts, n);
    scan_kernel   <<<1, 1024>>>();
    scatter_kernel<<<(groups + 255) / 256, 256>>>(n);
    pool_kernel   <<<NUM_CELLS / CPB, 256>>>(
        reinterpret_cast<const float4*>(feats),
        reinterpret_cast<float4*>(d_out));
}

// round 12
// speedup vs baseline: 1.3158x; 1.3158x over previous
#include <cuda_runtime.h>

// GridPooling: counting-sort by cell + warp-per-cell float4 gather-max.
// R11 = best-measured pieces reassembled:
//  - pre-phases from R9 (packed (cell,rank), register-prefetch coalesced scan
//    writing ONE offset array, uint4 4-wide scatter)   [~22us measured]
//  - pool from R7: warp-per-cell, 4-wide shuffle bodies, 128-thd blocks
//    [46.3us measured] + __ldcs streaming loads + exact tail + g_count
//    re-zeroing (no memset node).
// R10 lesson: scan's second, stride-128B store array cost ~18us of L1tex
// wavefronts on a single SM -- removed.

#define GRID_DIM   32
#define NUM_CELLS  (GRID_DIM * GRID_DIM * GRID_DIM)   // 32768
#define FEAT       128
#define MAX_POINTS (1 << 20)

__device__ int          g_count  [NUM_CELLS];    // zero at load; pool re-zeroes
__device__ int          g_offset [NUM_CELLS];
__device__ unsigned int g_cellrank[MAX_POINTS];  // cell | (rank << 16)
__device__ int          g_pidx   [MAX_POINTS];

__device__ __forceinline__ int cell_of(float x, float y, float z)
{
    int ix = __float2int_rd(x * (float)GRID_DIM);
    int iy = __float2int_rd(y * (float)GRID_DIM);
    int iz = __float2int_rd(z * (float)GRID_DIM);
    ix = min(max(ix, 0), GRID_DIM - 1);
    iy = min(max(iy, 0), GRID_DIM - 1);
    iz = min(max(iz, 0), GRID_DIM - 1);
    return ix * (GRID_DIM * GRID_DIM) + iy * GRID_DIM + iz;
}

// Phase 1: cell id + histogram; atomicAdd return value = within-cell rank
// (uniform 500K points over 32768 cells -> max count ~35 << 65536).
__global__ __launch_bounds__(256)
void cell_kernel(const float* __restrict__ pts, int n)
{
    const int q  = blockIdx.x * blockDim.x + threadIdx.x;
    const int p0 = q * 4;
    if (p0 >= n) return;

    if (p0 + 4 <= n) {
        const float4* p4 = reinterpret_cast<const float4*>(pts);
        float4 a = p4[q * 3 + 0];
        float4 b = p4[q * 3 + 1];
        float4 c = p4[q * 3 + 2];
        float xs[4] = {a.x, a.w, b.z, c.y};
        float ys[4] = {a.y, b.x, b.w, c.z};
        float zs[4] = {a.z, b.y, c.x, c.w};
        #pragma unroll
        for (int k = 0; k < 4; k++) {
            int c_ = cell_of(xs[k], ys[k], zs[k]);
            unsigned int r = (unsigned int)atomicAdd(&g_count[c_], 1);
            g_cellrank[p0 + k] = (unsigned int)c_ | (r << 16);
        }
    } else {
        for (int p = p0; p < n; p++) {
            int c_ = cell_of(pts[3 * p], pts[3 * p + 1], pts[3 * p + 2]);
            unsigned int r = (unsigned int)atomicAdd(&g_count[c_], 1);
            g_cellrank[p] = (unsigned int)c_ | (r << 16);
        }
    }
}

// Phase 2: exclusive scan of 32768 counts, one 1024-thread block.
// Thread t owns cells {t + j*1024}: loads AND stores coalesced (any
// bijective cell ordering is a valid sort layout). Counts prefetched
// into registers (MLP=32) before the serial local scan.
__global__ __launch_bounds__(1024)
void scan_kernel()
{
    __shared__ int warp_sums[32];
    const int t    = threadIdx.x;
    const int lane = t & 31;
    const int w    = t >> 5;

    int vals[32];
    #pragma unroll
    for (int j = 0; j < 32; j++)
        vals[j] = g_count[t + j * 1024];

    int local[32];
    int s = 0;
    #pragma unroll
    for (int j = 0; j < 32; j++) { local[j] = s; s += vals[j]; }

    int v = s;
    #pragma unroll
    for (int d = 1; d < 32; d <<= 1) {
        int nbr = __shfl_up_sync(0xffffffffu, v, d);
        if (lane >= d) v += nbr;
    }
    if (lane == 31) warp_sums[w] = v;
    __syncthreads();
    if (w == 0) {
        int x = warp_sums[lane];
        #pragma unroll
        for (int d = 1; d < 32; d <<= 1) {
            int nbr = __shfl_up_sync(0xffffffffu, x, d);
            if (lane >= d) x += nbr;
        }
        warp_sums[lane] = x;
    }
    __syncthreads();

    const int excl = v - s + (w > 0 ? warp_sums[w - 1] : 0);
    #pragma unroll
    for (int j = 0; j < 32; j++)
        g_offset[t + j * 1024] = excl + local[j];   // coalesced
}

// Phase 3: atomic-free scatter, 4 points per thread (uint4 metadata load,
// 4 independent offset loads in flight).
__global__ __launch_bounds__(256)
void scatter_kernel(int n)
{
    const int q  = blockIdx.x * blockDim.x + threadIdx.x;
    const int p0 = q * 4;
    if (p0 >= n) return;

    if (p0 + 4 <= n) {
        uint4 cr = reinterpret_cast<const uint4*>(g_cellrank)[q];
        int o0 = g_offset[cr.x & 0xffffu];
        int o1 = g_offset[cr.y & 0xffffu];
        int o2 = g_offset[cr.z & 0xffffu];
        int o3 = g_offset[cr.w & 0xffffu];
        g_pidx[o0 + (int)(cr.x >> 16)] = p0 + 0;
        g_pidx[o1 + (int)(cr.y >> 16)] = p0 + 1;
        g_pidx[o2 + (int)(cr.z >> 16)] = p0 + 2;
        g_pidx[o3 + (int)(cr.w >> 16)] = p0 + 3;
    } else {
        for (int p = p0; p < n; p++) {
            unsigned int cr = g_cellrank[p];
            g_pidx[g_offset[cr & 0xffffu] + (int)(cr >> 16)] = p;
        }
    }
}

// Phase 4: one warp per cell, lane = one float4 (warp covers the 512B row).
// Index list via shuffle broadcast; 4 independent LDG.128 (streaming hint)
// per step; exact tail. Zeroes g_count afterwards so the next graph replay
// starts from the all-zero invariant.
__device__ __forceinline__ float4 max4(float4 a, float4 b)
{
    return make_float4(fmaxf(a.x, b.x), fmaxf(a.y, b.y),
                       fmaxf(a.z, b.z), fmaxf(a.w, b.w));
}

__global__ __launch_bounds__(128)
void pool_kernel(const float4* __restrict__ feats4, float4* __restrict__ out4)
{
    const int warp = threadIdx.x >> 5;
    const int lane = threadIdx.x & 31;
    const int cell = blockIdx.x * 4 + warp;

    const int off = g_offset[cell];
    const int cnt = g_count[cell];

    float4 m = make_float4(0.f, 0.f, 0.f, 0.f);  // max(.,0) + empty cells

    for (int base = 0; base < cnt; base += 32) {
        const int chunk = min(32, cnt - base);
        int idx = 0;
        if (lane < chunk) idx = g_pidx[off + base + lane];

        int i = 0;
        for (; i + 4 <= chunk; i += 4) {
            int j0 = __shfl_sync(0xffffffffu, idx, i);
            int j1 = __shfl_sync(0xffffffffu, idx, i + 1);
            int j2 = __shfl_sync(0xffffffffu, idx, i + 2);
            int j3 = __shfl_sync(0xffffffffu, idx, i + 3);
            float4 a = __ldcs(&feats4[(size_t)j0 * (FEAT / 4) + lane]);
            float4 b = __ldcs(&feats4[(size_t)j1 * (FEAT / 4) + lane]);
            float4 c = __ldcs(&feats4[(size_t)j2 * (FEAT / 4) + lane]);
            float4 d = __ldcs(&feats4[(size_t)j3 * (FEAT / 4) + lane]);
            m = max4(m, max4(max4(a, b), max4(c, d)));
        }
        for (; i < chunk; i++) {
            int j = __shfl_sync(0xffffffffu, idx, i);
            m = max4(m, __ldcs(&feats4[(size_t)j * (FEAT / 4) + lane]));
        }
    }

    out4[(size_t)cell * (FEAT / 4) + lane] = m;

    if (lane == 0) g_count[cell] = 0;   // restore invariant for next replay
}

extern "C" void kernel_launch(void* const* d_in, const int* in_sizes, int n_in,
                              void* d_out, int out_size)
{
    const float* feats = (const float*)d_in[0];   // [N, 128]
    const float* pts   = (const float*)d_in[1];   // [N, 3]

    const int n = in_sizes[1] / 3;

    const int groups = (n + 3) / 4;
    cell_kernel   <<<(groups + 255) / 256, 256>>>(pts, n);
    scan_kernel   <<<1, 1024>>>();
    scatter_kernel<<<(groups + 255) / 256, 256>>>(n);
    pool_kernel   <<<NUM_CELLS / 4, 128>>>(
        reinterpret_cast<const float4*>(feats),
        reinterpret_cast<float4*>(d_out));
}

// round 13
// speedup vs baseline: 1.3574x; 1.0316x over previous
#include <cuda_runtime.h>

// GridPooling: direct fixed-capacity bucketing + warp-per-cell float4
// gather-max. TWO kernels.
//
// R12 vs R11 (65.8us): scan + scatter kernels eliminated. Phase 1 writes
// point indices straight into per-cell buckets (g_bucket[cell*CAP + rank],
// rank = atomicAdd return). Uniform 500K pts / 32768 cells -> max count
// ~40 << CAP=128; the r >= CAP path (signed-int atomicMax into a per-cell
// reserve row, folded by pool) keeps the kernel exact for ANY input.
// Pool restored to the measured-best R7 config: 4-wide clamped-shuffle
// bodies, plain LDG.128, 128-thread blocks (46.3us, occ 83%, DRAM 74%).
// R11 lesson: __ldcs raised regs 32->40 and cost 2us -- removed.

#define GRID_DIM   32
#define NUM_CELLS  (GRID_DIM * GRID_DIM * GRID_DIM)   // 32768
#define FEAT       128
#define CAP        128      // bucket capacity per cell

__device__ int g_count [NUM_CELLS];            // zero at load; pool re-zeroes
__device__ int g_bucket[NUM_CELLS * CAP];      // point indices per cell
__device__ int g_extra [NUM_CELLS * FEAT];     // overflow reserve (float bits,
                                               // zero-maintained invariant)

__device__ __forceinline__ int cell_of(float x, float y, float z)
{
    int ix = __float2int_rd(x * (float)GRID_DIM);
    int iy = __float2int_rd(y * (float)GRID_DIM);
    int iz = __float2int_rd(z * (float)GRID_DIM);
    ix = min(max(ix, 0), GRID_DIM - 1);
    iy = min(max(iy, 0), GRID_DIM - 1);
    iz = min(max(iz, 0), GRID_DIM - 1);
    return ix * (GRID_DIM * GRID_DIM) + iy * GRID_DIM + iz;
}

// Rare-path overflow: fold this point's features into the cell's reserve row
// via signed-int atomicMax (valid for floats >= 0; negatives lose to the 0
// init, matching max(pooled, 0)).
__device__ __noinline__ void overflow_point(const float* __restrict__ feats,
                                            int p, int cell)
{
    const float* row = feats + (size_t)p * FEAT;
    int* er = g_extra + (size_t)cell * FEAT;
    for (int f = 0; f < FEAT; f++) {
        float v = row[f];
        if (v > 0.0f) atomicMax(&er[f], __float_as_int(v));
    }
}

// Phase 1: cell id + histogram + direct bucket write. The atomicAdd return
// value is the bucket slot; consecutive ranks per cell keep the scattered
// writes sector-dense.
__global__ __launch_bounds__(256)
void cell_kernel(const float* __restrict__ pts,
                 const float* __restrict__ feats, int n)
{
    const int q  = blockIdx.x * blockDim.x + threadIdx.x;
    const int p0 = q * 4;
    if (p0 >= n) return;

    if (p0 + 4 <= n) {
        const float4* p4 = reinterpret_cast<const float4*>(pts);
        float4 a = p4[q * 3 + 0];
        float4 b = p4[q * 3 + 1];
        float4 c = p4[q * 3 + 2];
        float xs[4] = {a.x, a.w, b.z, c.y};
        float ys[4] = {a.y, b.x, b.w, c.z};
        float zs[4] = {a.z, b.y, c.x, c.w};
        #pragma unroll
        for (int k = 0; k < 4; k++) {
            int c_ = cell_of(xs[k], ys[k], zs[k]);
            int r  = atomicAdd(&g_count[c_], 1);
            if (r < CAP) g_bucket[c_ * CAP + r] = p0 + k;
            else         overflow_point(feats, p0 + k, c_);
        }
    } else {
        for (int p = p0; p < n; p++) {
            int c_ = cell_of(pts[3 * p], pts[3 * p + 1], pts[3 * p + 2]);
            int r  = atomicAdd(&g_count[c_], 1);
            if (r < CAP) g_bucket[c_ * CAP + r] = p;
            else         overflow_point(feats, p, c_);
        }
    }
}

// Phase 2: one warp per cell, lane = one float4 (warp covers the 512B row).
// Bucket indices via shuffle broadcast; 4 independent LDG.128 per step with
// clamped-duplicate tail (dupes are L1 hits; max is idempotent). Re-zeroes
// g_count (and g_extra if it was used) for the next graph replay.
__device__ __forceinline__ float4 max4(float4 a, float4 b)
{
    return make_float4(fmaxf(a.x, b.x), fmaxf(a.y, b.y),
                       fmaxf(a.z, b.z), fmaxf(a.w, b.w));
}

__global__ __launch_bounds__(128)
void pool_kernel(const float4* __restrict__ feats4, float4* __restrict__ out4)
{
    const int warp = threadIdx.x >> 5;
    const int lane = threadIdx.x & 31;
    const int cell = blockIdx.x * 4 + warp;

    const int cnt_raw = g_count[cell];

    float4 m = make_float4(0.f, 0.f, 0.f, 0.f);  // max(.,0) + empty cells

    if (cnt_raw > CAP) {          // rare-path: fold + re-zero reserve row
        int* er = g_extra + (size_t)cell * FEAT + lane * 4;
        float4 e = make_float4(__int_as_float(er[0]), __int_as_float(er[1]),
                               __int_as_float(er[2]), __int_as_float(er[3]));
        m = max4(m, e);
        er[0] = 0; er[1] = 0; er[2] = 0; er[3] = 0;
    }
    const int cnt = min(cnt_raw, CAP);
    const int* bkt = g_bucket + cell * CAP;

    for (int base = 0; base < cnt; base += 32) {
        const int chunk = min(32, cnt - base);
        int idx = bkt[base + min(lane, chunk - 1)];

        for (int i = 0; i < chunk; i += 4) {
            int j0 = __shfl_sync(0xffffffffu, idx, i);
            int j1 = __shfl_sync(0xffffffffu, idx, min(i + 1, chunk - 1));
            int j2 = __shfl_sync(0xffffffffu, idx, min(i + 2, chunk - 1));
            int j3 = __shfl_sync(0xffffffffu, idx, min(i + 3, chunk - 1));
            float4 a = feats4[(size_t)j0 * (FEAT / 4) + lane];
            float4 b = feats4[(size_t)j1 * (FEAT / 4) + lane];
            float4 c = feats4[(size_t)j2 * (FEAT / 4) + lane];
            float4 d = feats4[(size_t)j3 * (FEAT / 4) + lane];
            m = max4(m, max4(max4(a, b), max4(c, d)));
        }
    }

    out4[(size_t)cell * (FEAT / 4) + lane] = m;

    if (lane == 0) g_count[cell] = 0;   // restore invariant for next replay
}

extern "C" void kernel_launch(void* const* d_in, const int* in_sizes, int n_in,
                              void* d_out, int out_size)
{
    const float* feats = (const float*)d_in[0];   // [N, 128]
    const float* pts   = (const float*)d_in[1];   // [N, 3]

    const int n = in_sizes[1] / 3;

    const int groups = (n + 3) / 4;
    cell_kernel<<<(groups + 255) / 256, 256>>>(pts, feats, n);
    pool_kernel<<<NUM_CELLS / 4, 128>>>(
        reinterpret_cast<const float4*>(feats),
        reinterpret_cast<float4*>(d_out));
}